// round 11
// baseline (speedup 1.0000x reference)
#include <cuda_runtime.h>
#include <cstdint>

// Scratch: transposed weight [G][L] = [8][4096] floats (128 KB)
__device__ float g_wt[8 * 4096];

__global__ void transpose_w_kernel(const float* __restrict__ w) {
    int idx = blockIdx.x * blockDim.x + threadIdx.x;
    if (idx < 8 * 4096) {
        int g = idx >> 12;
        int l = idx & 4095;
        g_wt[idx] = w[l * 8 + g];
    }
}

static constexpr int CHUNK  = 256;  // floats per stage (1 KB)
static constexpr int NSTAGE = 3;
static constexpr int NCHUNK = 4096 / CHUNK;  // 16

__device__ __forceinline__ uint32_t smem_u32(const void* p) {
    uint32_t a;
    asm("{ .reg .u64 t; cvta.to.shared.u64 t, %1; cvt.u32.u64 %0, t; }"
        : "=r"(a) : "l"(p));
    return a;
}

// Block: g = bid & 7; warp w handles row (b_base + w)*8 + g.
// Per-warp 3-stage cp.async.bulk pipeline feeds x through smem;
// weight staged once per block (R5 path). Consume = LDS.128 + FMA.
__global__ __launch_bounds__(256) void grouped_fc_kernel(
    const float* __restrict__ x,
    const float* __restrict__ bias,
    float* __restrict__ out)
{
    __shared__ float4 w_sh[1024];                                   // 16 KB
    __shared__ __align__(16) float x_buf[8][NSTAGE][CHUNK];         // 24 KB
    __shared__ __align__(8) uint64_t mbar[8][NSTAGE];

    const int g      = blockIdx.x & 7;
    const int b_base = (blockIdx.x >> 3) << 3;
    const int warp   = threadIdx.x >> 5;
    const int lane   = threadIdx.x & 31;
    const int row    = (b_base + warp) * 8 + g;

    const uint32_t my_mbar = smem_u32(&mbar[warp][0]);
    const uint32_t my_buf  = smem_u32(&x_buf[warp][0][0]);

    if (lane == 0) {
        #pragma unroll
        for (int s = 0; s < NSTAGE; s++)
            asm volatile("mbarrier.init.shared.b64 [%0], 1;"
                         :: "r"(my_mbar + s * 8) : "memory");
    }

    // Weight fill: coalesced float4 from L2-resident transposed copy.
    const float4* __restrict__ wsrc =
        reinterpret_cast<const float4*>(g_wt + (g << 12));
    #pragma unroll
    for (int i = 0; i < 4; i++)
        w_sh[threadIdx.x + i * 256] = wsrc[threadIdx.x + i * 256];
    __syncthreads();   // mbars initialized + w_sh ready

    const float* __restrict__ xrow = x + (size_t)row * 4096;

    // Prologue: issue chunks 0..NSTAGE-2.
    if (lane == 0) {
        #pragma unroll
        for (int k = 0; k < NSTAGE - 1; k++) {
            uint32_t mb  = my_mbar + k * 8;
            uint32_t dst = my_buf + k * (CHUNK * 4);
            asm volatile("mbarrier.arrive.expect_tx.shared.b64 _, [%0], %1;"
                         :: "r"(mb), "r"(CHUNK * 4) : "memory");
            asm volatile(
                "cp.async.bulk.shared::cta.global.mbarrier::complete_tx::bytes "
                "[%0], [%1], %2, [%3];"
                :: "r"(dst), "l"(xrow + k * CHUNK), "r"(CHUNK * 4), "r"(mb)
                : "memory");
        }
    }

    float a0 = 0.f, a1 = 0.f, a2 = 0.f, a3 = 0.f;
    const float4* w4 = reinterpret_cast<const float4*>(w_sh);

    #pragma unroll
    for (int k = 0; k < NCHUNK; k++) {
        const int s   = k % NSTAGE;
        const int par = (k / NSTAGE) & 1;

        // Keep the pipe full: issue chunk k+NSTAGE-1 (its stage's previous
        // occupant, chunk k-1, was consumed last iteration).
        const int j = k + NSTAGE - 1;
        if (j < NCHUNK && lane == 0) {
            const int sj = j % NSTAGE;
            uint32_t mb  = my_mbar + sj * 8;
            uint32_t dst = my_buf + sj * (CHUNK * 4);
            asm volatile("mbarrier.arrive.expect_tx.shared.b64 _, [%0], %1;"
                         :: "r"(mb), "r"(CHUNK * 4) : "memory");
            asm volatile(
                "cp.async.bulk.shared::cta.global.mbarrier::complete_tx::bytes "
                "[%0], [%1], %2, [%3];"
                :: "r"(dst), "l"(xrow + j * CHUNK), "r"(CHUNK * 4), "r"(mb)
                : "memory");
        }

        // Wait for chunk k (acquire: orders TMA data before our LDS).
        {
            uint32_t mb = my_mbar + s * 8;
            uint32_t done;
            asm volatile(
                "{\n\t.reg .pred p;\n\t"
                "mbarrier.try_wait.parity.acquire.cta.shared::cta.b64 p, [%1], %2;\n\t"
                "selp.b32 %0, 1, 0, p;\n\t}"
                : "=r"(done) : "r"(mb), "r"(par) : "memory");
            if (!done) {
                asm volatile(
                    "{\n\t.reg .pred P1;\n\t"
                    "W_%=:\n\t"
                    "mbarrier.try_wait.parity.acquire.cta.shared::cta.b64 P1, [%0], %1, 0x989680;\n\t"
                    "@P1 bra.uni D_%=;\n\t"
                    "bra.uni W_%=;\n\t"
                    "D_%=:\n\t}"
                    :: "r"(mb), "r"(par) : "memory");
            }
        }

        // Consume: 256 floats = 2 float4 per lane, conflict-free LDS.128.
        const float4* xs4 =
            reinterpret_cast<const float4*>(&x_buf[warp][s][0]);
        #pragma unroll
        for (int i = 0; i < 2; i++) {
            float4 xv = xs4[i * 32 + lane];
            float4 wv = w4[k * 64 + i * 32 + lane];
            a0 = fmaf(xv.x, wv.x, a0);
            a1 = fmaf(xv.y, wv.y, a1);
            a2 = fmaf(xv.z, wv.z, a2);
            a3 = fmaf(xv.w, wv.w, a3);
        }
    }

    float ssum = (a0 + a1) + (a2 + a3);
    #pragma unroll
    for (int off = 16; off > 0; off >>= 1)
        ssum += __shfl_xor_sync(0xFFFFFFFFu, ssum, off);

    if (lane == 0)
        out[row] = ssum + __ldg(&bias[g]);
}

extern "C" void kernel_launch(void* const* d_in, const int* in_sizes, int n_in,
                              void* d_out, int out_size) {
    const float* x      = (const float*)d_in[0]; // [8192, 8, 4096]
    const float* weight = (const float*)d_in[1]; // [1, 4096, 8]
    const float* bias   = (const float*)d_in[2]; // [8]
    float* out          = (float*)d_out;         // [8192, 8]

    transpose_w_kernel<<<(8 * 4096 + 255) / 256, 256>>>(weight);

    // 8192 blocks: 1024 b-tiles x 8 groups; 8 warps per block.
    grouped_fc_kernel<<<8192, 256>>>(x, bias, out);
}

// round 12
// speedup vs baseline: 1.0121x; 1.0121x over previous
#include <cuda_runtime.h>
#include <cstdint>

// Scratch: transposed weight [G][L] = [8][4096] floats (128 KB)
__device__ float g_wt[8 * 4096];

__global__ void transpose_w_kernel(const float* __restrict__ w) {
    int idx = blockIdx.x * blockDim.x + threadIdx.x;
    if (idx < 8 * 4096) {
        int g = idx >> 12;
        int l = idx & 4095;
        g_wt[idx] = w[l * 8 + g];
    }
}

static constexpr int CHUNK  = 256;  // floats per stage (1 KB)
static constexpr int NSTAGE = 3;
static constexpr int NCHUNK = 4096 / CHUNK;  // 16

__device__ __forceinline__ uint32_t smem_u32(const void* p) {
    uint32_t a;
    asm("{ .reg .u64 t; cvta.to.shared.u64 t, %1; cvt.u32.u64 %0, t; }"
        : "=r"(a) : "l"(p));
    return a;
}

// Block: g = bid & 7; warp w handles row (b_base + w)*8 + g.
// Per-warp 3-stage cp.async.bulk pipeline feeds x through smem;
// weight staged once per block (R5 path). Consume = LDS.128 + FMA.
__global__ __launch_bounds__(256) void grouped_fc_kernel(
    const float* __restrict__ x,
    const float* __restrict__ bias,
    float* __restrict__ out)
{
    __shared__ float4 w_sh[1024];                                   // 16 KB
    __shared__ __align__(16) float x_buf[8][NSTAGE][CHUNK];         // 24 KB
    __shared__ __align__(8) uint64_t mbar[8][NSTAGE];

    const int g      = blockIdx.x & 7;
    const int b_base = (blockIdx.x >> 3) << 3;
    const int warp   = threadIdx.x >> 5;
    const int lane   = threadIdx.x & 31;
    const int row    = (b_base + warp) * 8 + g;

    const uint32_t my_mbar = smem_u32(&mbar[warp][0]);
    const uint32_t my_buf  = smem_u32(&x_buf[warp][0][0]);

    if (lane == 0) {
        #pragma unroll
        for (int s = 0; s < NSTAGE; s++)
            asm volatile("mbarrier.init.shared.b64 [%0], 1;"
                         :: "r"(my_mbar + s * 8) : "memory");
    }

    // Weight fill: coalesced float4 from L2-resident transposed copy.
    const float4* __restrict__ wsrc =
        reinterpret_cast<const float4*>(g_wt + (g << 12));
    #pragma unroll
    for (int i = 0; i < 4; i++)
        w_sh[threadIdx.x + i * 256] = wsrc[threadIdx.x + i * 256];
    __syncthreads();   // mbars initialized + w_sh ready

    const float* __restrict__ xrow = x + (size_t)row * 4096;

    // Prologue: issue chunks 0..NSTAGE-2.
    if (lane == 0) {
        #pragma unroll
        for (int k = 0; k < NSTAGE - 1; k++) {
            uint32_t mb  = my_mbar + k * 8;
            uint32_t dst = my_buf + k * (CHUNK * 4);
            asm volatile("mbarrier.arrive.expect_tx.shared.b64 _, [%0], %1;"
                         :: "r"(mb), "r"(CHUNK * 4) : "memory");
            asm volatile(
                "cp.async.bulk.shared::cta.global.mbarrier::complete_tx::bytes "
                "[%0], [%1], %2, [%3];"
                :: "r"(dst), "l"(xrow + k * CHUNK), "r"(CHUNK * 4), "r"(mb)
                : "memory");
        }
    }

    float a0 = 0.f, a1 = 0.f, a2 = 0.f, a3 = 0.f;
    const float4* w4 = reinterpret_cast<const float4*>(w_sh);

    #pragma unroll
    for (int k = 0; k < NCHUNK; k++) {
        const int s   = k % NSTAGE;
        const int par = (k / NSTAGE) & 1;

        // Keep the pipe full: issue chunk k+NSTAGE-1 (its stage's previous
        // occupant, chunk k-1, was consumed last iteration).
        const int j = k + NSTAGE - 1;
        if (j < NCHUNK && lane == 0) {
            const int sj = j % NSTAGE;
            uint32_t mb  = my_mbar + sj * 8;
            uint32_t dst = my_buf + sj * (CHUNK * 4);
            asm volatile("mbarrier.arrive.expect_tx.shared.b64 _, [%0], %1;"
                         :: "r"(mb), "r"(CHUNK * 4) : "memory");
            asm volatile(
                "cp.async.bulk.shared::cta.global.mbarrier::complete_tx::bytes "
                "[%0], [%1], %2, [%3];"
                :: "r"(dst), "l"(xrow + j * CHUNK), "r"(CHUNK * 4), "r"(mb)
                : "memory");
        }

        // Wait for chunk k (acquire: orders TMA data before our LDS).
        {
            uint32_t mb = my_mbar + s * 8;
            uint32_t done;
            asm volatile(
                "{\n\t.reg .pred p;\n\t"
                "mbarrier.try_wait.parity.acquire.cta.shared::cta.b64 p, [%1], %2;\n\t"
                "selp.b32 %0, 1, 0, p;\n\t}"
                : "=r"(done) : "r"(mb), "r"(par) : "memory");
            if (!done) {
                asm volatile(
                    "{\n\t.reg .pred P1;\n\t"
                    "W_%=:\n\t"
                    "mbarrier.try_wait.parity.acquire.cta.shared::cta.b64 P1, [%0], %1, 0x989680;\n\t"
                    "@P1 bra.uni D_%=;\n\t"
                    "bra.uni W_%=;\n\t"
                    "D_%=:\n\t}"
                    :: "r"(mb), "r"(par) : "memory");
            }
        }

        // Consume: 256 floats = 2 float4 per lane, conflict-free LDS.128.
        const float4* xs4 =
            reinterpret_cast<const float4*>(&x_buf[warp][s][0]);
        #pragma unroll
        for (int i = 0; i < 2; i++) {
            float4 xv = xs4[i * 32 + lane];
            float4 wv = w4[k * 64 + i * 32 + lane];
            a0 = fmaf(xv.x, wv.x, a0);
            a1 = fmaf(xv.y, wv.y, a1);
            a2 = fmaf(xv.z, wv.z, a2);
            a3 = fmaf(xv.w, wv.w, a3);
        }
    }

    float ssum = (a0 + a1) + (a2 + a3);
    #pragma unroll
    for (int off = 16; off > 0; off >>= 1)
        ssum += __shfl_xor_sync(0xFFFFFFFFu, ssum, off);

    if (lane == 0)
        out[row] = ssum + __ldg(&bias[g]);
}

extern "C" void kernel_launch(void* const* d_in, const int* in_sizes, int n_in,
                              void* d_out, int out_size) {
    const float* x      = (const float*)d_in[0]; // [8192, 8, 4096]
    const float* weight = (const float*)d_in[1]; // [1, 4096, 8]
    const float* bias   = (const float*)d_in[2]; // [8]
    float* out          = (float*)d_out;         // [8192, 8]

    transpose_w_kernel<<<(8 * 4096 + 255) / 256, 256>>>(weight);

    // 8192 blocks: 1024 b-tiles x 8 groups; 8 warps per block.
    grouped_fc_kernel<<<8192, 256>>>(x, bias, out);
}

// round 13
// speedup vs baseline: 1.8370x; 1.8149x over previous
#include <cuda_runtime.h>

// Scratch: transposed weight [G][L] = [8][4096] floats (128 KB)
__device__ float g_wt[8 * 4096];

__global__ void transpose_w_kernel(const float* __restrict__ w) {
    int idx = blockIdx.x * blockDim.x + threadIdx.x;
    if (idx < 8 * 4096) {
        int g = idx >> 12;        // / 4096
        int l = idx & 4095;       // % 4096
        g_wt[idx] = w[l * 8 + g]; // w is [L, G]
    }
}

// Block layout: g = bid & 7; warps 0..7 handle b = (bid>>3)*8 + warp.
// One 16KB weight row (for g) is staged in smem once per block, so the
// inner loop does 32 x-LDG.128 + 32 conflict-free LDS.128 per warp.
// Measured: 32 regs, 90.7% occ, 90.3% DRAM — HBM-ceiling-bound.
__global__ __launch_bounds__(256) void grouped_fc_kernel(
    const float* __restrict__ x,
    const float* __restrict__ bias,
    float* __restrict__ out)
{
    __shared__ float4 w_sh[1024];  // 4096 floats = 16 KB

    const int g      = blockIdx.x & 7;
    const int b_base = (blockIdx.x >> 3) << 3;

    // Cooperative coalesced fill from L2-resident transposed weight.
    const float4* __restrict__ wsrc =
        reinterpret_cast<const float4*>(g_wt + (g << 12));
    #pragma unroll
    for (int i = 0; i < 4; i++)
        w_sh[threadIdx.x + i * 256] = wsrc[threadIdx.x + i * 256];
    __syncthreads();

    const int warp = threadIdx.x >> 5;  // 0..7
    const int lane = threadIdx.x & 31;
    const int row  = (b_base + warp) * 8 + g;

    const float4* __restrict__ xp =
        reinterpret_cast<const float4*>(x + (size_t)row * 4096) + lane;

    float a0 = 0.f, a1 = 0.f, a2 = 0.f, a3 = 0.f;

    // 4096 elems / (32 lanes * 4 per float4) = 32 iterations.
    #pragma unroll 8
    for (int i = 0; i < 32; i++) {
        float4 xv = xp[i * 32];
        float4 wv = w_sh[lane + i * 32];   // conflict-free LDS.128
        a0 = fmaf(xv.x, wv.x, a0);
        a1 = fmaf(xv.y, wv.y, a1);
        a2 = fmaf(xv.z, wv.z, a2);
        a3 = fmaf(xv.w, wv.w, a3);
    }

    float s = (a0 + a1) + (a2 + a3);
    #pragma unroll
    for (int off = 16; off > 0; off >>= 1)
        s += __shfl_xor_sync(0xFFFFFFFFu, s, off);

    if (lane == 0)
        out[row] = s + __ldg(&bias[g]);
}

extern "C" void kernel_launch(void* const* d_in, const int* in_sizes, int n_in,
                              void* d_out, int out_size) {
    const float* x      = (const float*)d_in[0]; // [8192, 8, 4096]
    const float* weight = (const float*)d_in[1]; // [1, 4096, 8]
    const float* bias   = (const float*)d_in[2]; // [8]
    float* out          = (float*)d_out;         // [8192, 8]

    transpose_w_kernel<<<(8 * 4096 + 255) / 256, 256>>>(weight);

    // 8192 blocks: 1024 b-tiles x 8 groups; 8 warps per block.
    grouped_fc_kernel<<<8192, 256>>>(x, bias, out);
}